// round 3
// baseline (speedup 1.0000x reference)
#include <cuda_runtime.h>
#include <math.h>

// Problem constants (fixed by this dataset instance)
constexpr int B = 16, P = 19248, C = 81, G = 16;
constexpr float VAR0 = 0.1f, VAR1 = 0.2f;
constexpr float POS_T = 0.5f, NEG_T = 0.4f;
constexpr int   NPR = 3;
constexpr float BBOX_ALPHA = 1.5f, CONF_ALPHA = 1.0f;

// -------- scratch (device globals; no allocation allowed) --------
__device__ float              g_btover[B * P];
__device__ int                g_btidx [B * P];
__device__ unsigned long long g_bestgt[B * G];
__device__ float              g_sl1   [B * P];
__device__ unsigned           g_lcbits[B * P];
__device__ float              g_ce    [B * P];
__device__ unsigned char      g_state [B * P];   // 0=neg(conf_t==0), 1=pos, 2=neutral
__device__ int                g_numpos[B];
__device__ unsigned           g_T     [B];
__device__ int                g_cutoff[B];
__device__ double             g_acc   [2];

// -------- kernel 0: reset per-launch accumulators --------
__global__ void k_reset() {
    int t = threadIdx.x;
    if (t < B * G) g_bestgt[t] = 0ULL;
    if (t < B)     g_numpos[t] = 0;
    if (t < 2)     g_acc[t]    = 0.0;
}

// -------- kernel 1: per-prior match + per-GT best prior --------
__global__ void k_match(const float* __restrict__ priors,
                        const float* __restrict__ gtb) {
    __shared__ float sg[G * 4];
    __shared__ float sga[G];
    __shared__ unsigned long long sbest[G];
    int b = blockIdx.y;
    int t = threadIdx.x;
    if (t < G * 4) sg[t] = gtb[b * G * 4 + t];
    if (t < G)     sbest[t] = 0ULL;
    __syncthreads();
    if (t < G)     sga[t] = (sg[t*4+2] - sg[t*4+0]) * (sg[t*4+3] - sg[t*4+1]);
    __syncthreads();

    int p = blockIdx.x * blockDim.x + t;
    if (p < P) {
        const float* pr = priors + ((size_t)b * P + p) * 4;
        float cx = pr[0], cy = pr[1], w = pr[2], h = pr[3];
        float bx1 = cx - 0.5f * w, by1 = cy - 0.5f * h;
        float bx2 = cx + 0.5f * w, by2 = cy + 0.5f * h;
        float areaB = w * h;
        float bo = -1.0f; int bi = 0;
        #pragma unroll
        for (int g = 0; g < G; g++) {
            float gx1 = sg[g*4+0], gy1 = sg[g*4+1];
            float gx2 = sg[g*4+2], gy2 = sg[g*4+3];
            float iw = fmaxf(fminf(gx2, bx2) - fmaxf(gx1, bx1), 0.0f);
            float ih = fmaxf(fminf(gy2, by2) - fmaxf(gy1, by1), 0.0f);
            float inter = iw * ih;
            float iou = inter / fmaxf(sga[g] + areaB - inter, 1e-10f);
            if (iou > bo) { bo = iou; bi = g; }   // first-index argmax
            unsigned long long key =
                ((unsigned long long)__float_as_uint(iou) << 32) |
                (unsigned long long)(0xFFFFFFFFu - (unsigned)p);  // max iou, then min p
            atomicMax(&sbest[g], key);
        }
        g_btover[b * P + p] = bo;
        g_btidx [b * P + p] = bi;
    }
    __syncthreads();
    if (t < G) atomicMax(&g_bestgt[b * G + t], sbest[t]);
}

// -------- kernel 2: force-match best prior per GT (sequential, last g wins) --------
__global__ void k_force() {
    int b = threadIdx.x;
    if (b < B) {
        for (int g = 0; g < G; g++) {
            unsigned long long key = g_bestgt[b * G + g];
            int p = (int)(0xFFFFFFFFu - (unsigned)(key & 0xFFFFFFFFull));
            g_btover[b * P + p] = 2.0f;
            g_btidx [b * P + p] = g;
        }
    }
}

// -------- kernel 3: per-prior conf loss pieces + loc smooth-L1 (warp per prior) --------
__global__ void k_conf(const float* __restrict__ conf,
                       const float* __restrict__ loc,
                       const float* __restrict__ priors,
                       const float* __restrict__ gtb,
                       const int*   __restrict__ gtl) {
    int b    = blockIdx.y;
    int wid  = threadIdx.x >> 5;
    int lane = threadIdx.x & 31;
    int p    = blockIdx.x * 8 + wid;
    __shared__ int s_pos[8];

    bool is_pos = false;
    if (p < P) {
        const float* cp = conf + ((size_t)b * P + p) * C;
        float v0 = (lane      < C) ? cp[lane]      : -1e30f;
        float v1 = (lane + 32 < C) ? cp[lane + 32] : -1e30f;
        float v2 = (lane + 64 < C) ? cp[lane + 64] : -1e30f;
        float m = fmaxf(v0, fmaxf(v1, v2));
        #pragma unroll
        for (int o = 16; o > 0; o >>= 1) m = fmaxf(m, __shfl_xor_sync(0xffffffffu, m, o));
        float s = __expf(v0 - m) + __expf(v1 - m) + __expf(v2 - m);
        #pragma unroll
        for (int o = 16; o > 0; o >>= 1) s += __shfl_xor_sync(0xffffffffu, s, o);
        float lse = m + logf(s);

        if (lane == 0) {
            int idx = b * P + p;
            float bo = g_btover[idx];
            int   bi = g_btidx[idx];
            int  lab = gtl[b * G + bi];
            int conf_t = (bo < POS_T) ? ((bo < NEG_T) ? 0 : -1) : lab;
            bool pos = conf_t > 0;
            is_pos = pos;
            int  tgt = pos ? conf_t : 0;
            float ce = lse - cp[tgt];
            float lc = (pos || conf_t < 0) ? 0.0f : (lse - v0);   // v0 at lane0 == conf[...,0]
            g_ce[idx]     = ce;
            g_lcbits[idx] = __float_as_uint(lc);                  // lc >= 0: bits monotonic
            g_state[idx]  = pos ? 1 : (conf_t < 0 ? 2 : 0);
            float sl = 0.0f;
            if (pos) {
                const float* pr = priors + ((size_t)b * P + p) * 4;
                const float* gb = gtb + ((size_t)b * G + bi) * 4;
                const float* ld = loc + ((size_t)b * P + p) * 4;
                float pcx = pr[0], pcy = pr[1], pw = pr[2], ph = pr[3];
                float t0 = ((gb[0] + gb[2]) * 0.5f - pcx) / (VAR0 * pw);
                float t1 = ((gb[1] + gb[3]) * 0.5f - pcy) / (VAR0 * ph);
                float t2 = logf(fmaxf((gb[2] - gb[0]) / pw, 1e-8f)) / VAR1;
                float t3 = logf(fmaxf((gb[3] - gb[1]) / ph, 1e-8f)) / VAR1;
                float d;
                d = ld[0] - t0; sl += (fabsf(d) < 1.0f) ? 0.5f * d * d : fabsf(d) - 0.5f;
                d = ld[1] - t1; sl += (fabsf(d) < 1.0f) ? 0.5f * d * d : fabsf(d) - 0.5f;
                d = ld[2] - t2; sl += (fabsf(d) < 1.0f) ? 0.5f * d * d : fabsf(d) - 0.5f;
                d = ld[3] - t3; sl += (fabsf(d) < 1.0f) ? 0.5f * d * d : fabsf(d) - 0.5f;
            }
            g_sl1[idx] = sl;
        }
    }
    // warp-level positive count (lane 0 holds the flag)
    unsigned bal = __ballot_sync(0xffffffffu, is_pos);
    if (lane == 0) s_pos[wid] = (bal & 1u) ? 1 : 0;
    __syncthreads();
    if (threadIdx.x == 0) {
        int c = s_pos[0] + s_pos[1] + s_pos[2] + s_pos[3]
              + s_pos[4] + s_pos[5] + s_pos[6] + s_pos[7];
        if (c) atomicAdd(&g_numpos[b], c);
    }
}

// -------- kernel 4: per-image radix-select k-th largest loss_c + tie cutoff --------
__global__ void k_select() {
    int b = blockIdx.x;
    int t = threadIdx.x;
    __shared__ unsigned hist[256];
    __shared__ unsigned s_prefix;
    __shared__ int s_rem;
    __shared__ int s_cnt;

    int k = NPR * g_numpos[b];
    if (k > P - 1) k = P - 1;
    if (t == 0) { s_prefix = 0; s_rem = k; }
    __syncthreads();

    for (int byte = 3; byte >= 0; byte--) {
        hist[t] = 0;
        __syncthreads();
        unsigned prefix = s_prefix;
        int shift = byte * 8;
        for (int p = t; p < P; p += 256) {
            unsigned long long v = (unsigned long long)g_lcbits[b * P + p];
            if ((unsigned)(v >> (shift + 8)) == prefix)
                atomicAdd(&hist[(unsigned)(v >> shift) & 0xFFu], 1u);
        }
        __syncthreads();
        if (t == 0) {
            int rem = s_rem;
            unsigned pr = s_prefix;
            for (int bin = 255; bin >= 0; bin--) {
                int c = (int)hist[bin];
                if (rem > c) { rem -= c; }
                else         { pr = (pr << 8) | (unsigned)bin; break; }
            }
            s_prefix = pr; s_rem = rem;
        }
        __syncthreads();
    }
    unsigned T = s_prefix;
    int needed = s_rem;   // >= 1 since k >= 3 (num_pos >= 1 via forced matches)

    // binary search for cutoff index: smallest m with |{p<=m : bits==T}| >= needed
    int lo = 0, hi = P - 1;
    while (lo < hi) {
        int mid = (lo + hi) >> 1;
        if (t == 0) s_cnt = 0;
        __syncthreads();
        int c = 0;
        for (int p = t; p <= mid; p += 256)
            if (g_lcbits[b * P + p] == T) c++;
        if (c) atomicAdd(&s_cnt, c);
        __syncthreads();
        if (s_cnt >= needed) hi = mid; else lo = mid + 1;
        __syncthreads();
    }
    if (t == 0) { g_T[b] = T; g_cutoff[b] = lo; }
}

// -------- kernel 5: final per-prior contributions + reduction --------
__global__ void k_final() {
    int b = blockIdx.y;
    int p = blockIdx.x * 256 + threadIdx.x;
    float cB = 0.0f, cC = 0.0f;
    if (p < P) {
        int idx = b * P + p;
        int st = g_state[idx];
        unsigned bits = g_lcbits[idx];
        unsigned T = g_T[b];
        int cut = g_cutoff[b];
        bool neg = (st == 0) && (bits > T || (bits == T && p <= cut));
        bool pos = (st == 1);
        if (pos) cB = g_sl1[idx] / (float)max(g_numpos[b], 1);
        if (pos || neg) cC = g_ce[idx];
    }
    __shared__ float rB[256], rC[256];
    rB[threadIdx.x] = cB; rC[threadIdx.x] = cC;
    __syncthreads();
    for (int s = 128; s > 0; s >>= 1) {
        if (threadIdx.x < s) {
            rB[threadIdx.x] += rB[threadIdx.x + s];
            rC[threadIdx.x] += rC[threadIdx.x + s];
        }
        __syncthreads();
    }
    if (threadIdx.x == 0) {
        atomicAdd(&g_acc[0], (double)rB[0]);
        atomicAdd(&g_acc[1], (double)rC[0]);
    }
}

// -------- kernel 6: write output --------
__global__ void k_out(float* out) {
    if (threadIdx.x == 0) {
        out[0] = (float)(g_acc[0] * (double)BBOX_ALPHA / (double)B);
        out[1] = (float)(g_acc[1] * (double)CONF_ALPHA / (double)B);
    }
}

extern "C" void kernel_launch(void* const* d_in, const int* in_sizes, int n_in,
                              void* d_out, int out_size) {
    const float* loc    = (const float*)d_in[0];
    const float* conf   = (const float*)d_in[1];
    const float* priors = (const float*)d_in[2];
    const float* gtb    = (const float*)d_in[3];
    const int*   gtl    = (const int*)d_in[4];
    float* out = (float*)d_out;

    k_reset<<<1, 256>>>();
    {
        dim3 grid((P + 255) / 256, B);
        k_match<<<grid, 256>>>(priors, gtb);
    }
    k_force<<<1, B>>>();
    {
        dim3 grid((P + 7) / 8, B);
        k_conf<<<grid, 256>>>(conf, loc, priors, gtb, gtl);
    }
    k_select<<<B, 256>>>();
    {
        dim3 grid((P + 255) / 256, B);
        k_final<<<grid, 256>>>();
    }
    k_out<<<1, 1>>>(out);
}

// round 4
// speedup vs baseline: 1.3462x; 1.3462x over previous
#include <cuda_runtime.h>
#include <math.h>

// Problem constants (fixed by this dataset instance)
constexpr int B = 16, P = 19248, C = 81, G = 16;
constexpr float VAR0 = 0.1f, VAR1 = 0.2f;
constexpr float POS_T = 0.5f, NEG_T = 0.4f;
constexpr int   NPR = 3;
constexpr float BBOX_ALPHA = 1.5f, CONF_ALPHA = 1.0f;

constexpr int TILE = 48;            // priors per k_conf block (48*401 == P exactly)
constexpr int CONF_THREADS = 384;   // 8 threads per prior row
constexpr int SEL_THREADS = 1024;

// -------- scratch (device globals; no allocation allowed) --------
__device__ float              g_btover[B * P];
__device__ int                g_btidx [B * P];
__device__ unsigned long long g_bestgt[B * G];
__device__ float              g_sl1   [B * P];
__device__ unsigned           g_lcbits[B * P];
__device__ float              g_ce    [B * P];
__device__ unsigned char      g_state [B * P];   // 0=neg(conf_t==0), 1=pos, 2=neutral
__device__ int                g_numpos[B];
__device__ double             g_acc   [2];
__device__ unsigned           g_done;

// -------- kernel 0: reset per-launch accumulators --------
__global__ void k_reset() {
    int t = threadIdx.x;
    if (t < B * G) g_bestgt[t] = 0ULL;
    if (t < B)     g_numpos[t] = 0;
    if (t < 2)     g_acc[t]    = 0.0;
    if (t == 0)    g_done      = 0u;
}

// -------- kernel 1: per-prior match + per-GT best prior --------
__global__ void k_match(const float4* __restrict__ priors4,
                        const float* __restrict__ gtb) {
    __shared__ float sg[G * 4];
    __shared__ float sga[G];
    __shared__ unsigned long long sbest[G];
    int b = blockIdx.y;
    int t = threadIdx.x;
    if (t < G * 4) sg[t] = gtb[b * G * 4 + t];
    if (t < G)     sbest[t] = 0ULL;
    __syncthreads();
    if (t < G)     sga[t] = (sg[t*4+2] - sg[t*4+0]) * (sg[t*4+3] - sg[t*4+1]);
    __syncthreads();

    int p = blockIdx.x * blockDim.x + t;
    if (p < P) {
        float4 pr = priors4[(size_t)b * P + p];
        float cx = pr.x, cy = pr.y, w = pr.z, h = pr.w;
        float bx1 = cx - 0.5f * w, by1 = cy - 0.5f * h;
        float bx2 = cx + 0.5f * w, by2 = cy + 0.5f * h;
        float areaB = w * h;
        float bo = -1.0f; int bi = 0;
        #pragma unroll
        for (int g = 0; g < G; g++) {
            float gx1 = sg[g*4+0], gy1 = sg[g*4+1];
            float gx2 = sg[g*4+2], gy2 = sg[g*4+3];
            float iw = fmaxf(fminf(gx2, bx2) - fmaxf(gx1, bx1), 0.0f);
            float ih = fmaxf(fminf(gy2, by2) - fmaxf(gy1, by1), 0.0f);
            float inter = iw * ih;
            float iou = inter / fmaxf(sga[g] + areaB - inter, 1e-10f);
            if (iou > bo) { bo = iou; bi = g; }   // first-index argmax
            unsigned long long key =
                ((unsigned long long)__float_as_uint(iou) << 32) |
                (unsigned long long)(0xFFFFFFFFu - (unsigned)p);  // max iou, then min p
            atomicMax(&sbest[g], key);
        }
        g_btover[b * P + p] = bo;
        g_btidx [b * P + p] = bi;
    }
    __syncthreads();
    if (t < G) atomicMax(&g_bestgt[b * G + t], sbest[t]);
}

// -------- kernel 2: conf loss pieces + force-match + loc smooth-L1 --------
// Block: 384 threads, one image-tile of 48 priors. Stage conf tile to smem
// via coalesced float4, reduce 8 threads per row.
__global__ __launch_bounds__(CONF_THREADS)
void k_conf(const float* __restrict__ conf,
            const float* __restrict__ loc,
            const float* __restrict__ priors,
            const float* __restrict__ gtb,
            const int*   __restrict__ gtl) {
    __shared__ float sconf[TILE * C];          // 15552 B
    __shared__ int   sbestp[G];
    __shared__ int   slab[G];
    __shared__ float sgb[G * 4];
    __shared__ int   s_pos[CONF_THREADS / 32];

    int b    = blockIdx.y;
    int tile = blockIdx.x;
    int t    = threadIdx.x;

    // stage GT metadata
    if (t < G) {
        unsigned long long key = g_bestgt[b * G + t];
        sbestp[t] = (int)(0xFFFFFFFFu - (unsigned)(key & 0xFFFFFFFFull));
        slab[t]   = gtl[b * G + t];
    }
    if (t < G * 4) sgb[t] = gtb[b * G * 4 + t];

    // stage conf tile: contiguous TILE*C floats, 16B aligned
    {
        const float4* src = (const float4*)(conf + ((size_t)b * P + (size_t)tile * TILE) * C);
        float4* dst = (float4*)sconf;
        constexpr int N4 = TILE * C / 4;   // 972
        for (int i = t; i < N4; i += CONF_THREADS) dst[i] = src[i];
    }
    __syncthreads();

    int row = t >> 3;           // 0..47
    int sub = t & 7;            // 0..7
    const float* srow = sconf + row * C;

    float v[11];
    #pragma unroll
    for (int i = 0; i < 11; i++) {
        int j = sub + i * 8;
        v[i] = (j < C) ? srow[j] : -1e30f;
    }
    float m = v[0];
    #pragma unroll
    for (int i = 1; i < 11; i++) m = fmaxf(m, v[i]);
    m = fmaxf(m, __shfl_xor_sync(0xffffffffu, m, 1));
    m = fmaxf(m, __shfl_xor_sync(0xffffffffu, m, 2));
    m = fmaxf(m, __shfl_xor_sync(0xffffffffu, m, 4));
    float s = 0.0f;
    #pragma unroll
    for (int i = 0; i < 11; i++) s += __expf(v[i] - m);
    s += __shfl_xor_sync(0xffffffffu, s, 1);
    s += __shfl_xor_sync(0xffffffffu, s, 2);
    s += __shfl_xor_sync(0xffffffffu, s, 4);

    bool is_pos = false;
    if (sub == 0) {
        float lse = m + logf(s);
        int p   = tile * TILE + row;
        int idx = b * P + p;
        float bo = g_btover[idx];
        int   bi = g_btidx[idx];
        // force-match membership (ascending g, last wins == sequential scatter)
        #pragma unroll
        for (int g = 0; g < G; g++) {
            if (sbestp[g] == p) { bo = 2.0f; bi = g; }
        }
        int lab = slab[bi];
        int conf_t = (bo < POS_T) ? ((bo < NEG_T) ? 0 : -1) : lab;
        bool pos = conf_t > 0;
        is_pos = pos;
        int tgt = pos ? conf_t : 0;
        float ce = lse - srow[tgt];
        float lc = (pos || conf_t < 0) ? 0.0f : (lse - srow[0]);
        g_ce[idx]     = ce;
        g_lcbits[idx] = __float_as_uint(lc);      // lc >= 0: bits monotonic
        g_state[idx]  = pos ? 1 : (conf_t < 0 ? 2 : 0);
        float sl = 0.0f;
        if (pos) {
            const float4* pr4 = (const float4*)(priors + (size_t)idx * 4);
            const float4* ld4 = (const float4*)(loc    + (size_t)idx * 4);
            float4 pr = *pr4;
            float4 ld = *ld4;
            float gx1 = sgb[bi*4+0], gy1 = sgb[bi*4+1];
            float gx2 = sgb[bi*4+2], gy2 = sgb[bi*4+3];
            float t0 = ((gx1 + gx2) * 0.5f - pr.x) / (VAR0 * pr.z);
            float t1 = ((gy1 + gy2) * 0.5f - pr.y) / (VAR0 * pr.w);
            float t2 = logf(fmaxf((gx2 - gx1) / pr.z, 1e-8f)) / VAR1;
            float t3 = logf(fmaxf((gy2 - gy1) / pr.w, 1e-8f)) / VAR1;
            float d;
            d = ld.x - t0; sl += (fabsf(d) < 1.0f) ? 0.5f * d * d : fabsf(d) - 0.5f;
            d = ld.y - t1; sl += (fabsf(d) < 1.0f) ? 0.5f * d * d : fabsf(d) - 0.5f;
            d = ld.z - t2; sl += (fabsf(d) < 1.0f) ? 0.5f * d * d : fabsf(d) - 0.5f;
            d = ld.w - t3; sl += (fabsf(d) < 1.0f) ? 0.5f * d * d : fabsf(d) - 0.5f;
        }
        g_sl1[idx] = sl;
    }
    // count positives: only lanes with sub==0 can be true
    unsigned bal = __ballot_sync(0xffffffffu, is_pos);
    if ((t & 31) == 0) s_pos[t >> 5] = __popc(bal);
    __syncthreads();
    if (t == 0) {
        int c = 0;
        #pragma unroll
        for (int w = 0; w < CONF_THREADS / 32; w++) c += s_pos[w];
        if (c) atomicAdd(&g_numpos[b], c);
    }
}

// -------- kernel 3: per-image radix select + tie cutoff + final sums + out --------
__global__ __launch_bounds__(SEL_THREADS)
void k_selfin(float* __restrict__ out) {
    int b = blockIdx.x;
    int t = threadIdx.x;
    __shared__ unsigned hist[256];
    __shared__ unsigned suf[257];
    __shared__ unsigned s_prefix;
    __shared__ int s_rem;
    __shared__ int s_cut;
    __shared__ int sc[SEL_THREADS];
    __shared__ float sB, sC;

    const unsigned* lc = g_lcbits + b * P;
    int numpos = g_numpos[b];
    int k = NPR * numpos;
    if (k > P - 1) k = P - 1;
    if (t == 0) { s_prefix = 0; s_rem = k; sB = 0.0f; sC = 0.0f; }
    __syncthreads();

    // 4 x 8-bit radix passes, descending
    for (int byte = 3; byte >= 0; byte--) {
        if (t < 256) hist[t] = 0;
        __syncthreads();
        unsigned prefix = s_prefix;
        int rem = s_rem;
        int shift = byte * 8;
        bool top = (byte == 3);
        for (int p = t; p < P; p += SEL_THREADS) {
            unsigned v = lc[p];
            if (top || (v >> (shift + 8)) == prefix)
                atomicAdd(&hist[(v >> shift) & 0xFFu], 1u);
        }
        __syncthreads();
        if (t < 256) {
            unsigned ssum = 0;
            for (int bin = 255; bin >= t; bin--) ssum += hist[bin];
            suf[t] = ssum;
        }
        if (t == 0) suf[256] = 0;
        __syncthreads();
        if (t < 256) {
            unsigned above = suf[t + 1];
            if (above < (unsigned)rem && (unsigned)rem <= suf[t]) {
                s_prefix = (prefix << 8) | (unsigned)t;
                s_rem = rem - (int)above;
            }
        }
        __syncthreads();
    }
    unsigned T = s_prefix;
    int needed = s_rem;   // >= 1

    // tie cutoff: blocked partition preserves index order
    constexpr int CHUNK = (P + SEL_THREADS - 1) / SEL_THREADS;  // 19
    int beg = t * CHUNK;
    int end = min(beg + CHUNK, P);
    int cnt = 0;
    for (int p = beg; p < end; p++)
        if (lc[p] == T) cnt++;
    sc[t] = cnt;
    __syncthreads();
    // Hillis-Steele inclusive scan over 1024 counts
    for (int off = 1; off < SEL_THREADS; off <<= 1) {
        int add = (t >= off) ? sc[t - off] : 0;
        __syncthreads();
        sc[t] += add;
        __syncthreads();
    }
    int incl = sc[t];
    int excl = incl - cnt;
    if (excl < needed && needed <= incl) {
        int want = needed - excl;
        for (int p = beg; p < end; p++) {
            if (lc[p] == T) {
                if (--want == 0) { s_cut = p; break; }
            }
        }
    }
    __syncthreads();
    int cut = s_cut;

    // final per-prior sums for this image
    float invnp = 1.0f / (float)max(numpos, 1);
    float cB = 0.0f, cC = 0.0f;
    for (int p = t; p < P; p += SEL_THREADS) {
        int idx = b * P + p;
        int st = g_state[idx];
        unsigned bits = g_lcbits[idx];
        bool neg = (st == 0) && (bits > T || (bits == T && p <= cut));
        bool pos = (st == 1);
        if (pos) cB += g_sl1[idx] * invnp;
        if (pos || neg) cC += g_ce[idx];
    }
    // warp reduce then smem atomics
    #pragma unroll
    for (int o = 16; o > 0; o >>= 1) {
        cB += __shfl_xor_sync(0xffffffffu, cB, o);
        cC += __shfl_xor_sync(0xffffffffu, cC, o);
    }
    if ((t & 31) == 0) {
        atomicAdd(&sB, cB);
        atomicAdd(&sC, cC);
    }
    __syncthreads();
    if (t == 0) {
        atomicAdd(&g_acc[0], (double)sB);
        atomicAdd(&g_acc[1], (double)sC);
        __threadfence();
        unsigned old = atomicAdd(&g_done, 1u);
        if (old == B - 1) {
            out[0] = (float)(g_acc[0] * (double)BBOX_ALPHA / (double)B);
            out[1] = (float)(g_acc[1] * (double)CONF_ALPHA / (double)B);
        }
    }
}

extern "C" void kernel_launch(void* const* d_in, const int* in_sizes, int n_in,
                              void* d_out, int out_size) {
    const float* loc    = (const float*)d_in[0];
    const float* conf   = (const float*)d_in[1];
    const float* priors = (const float*)d_in[2];
    const float* gtb    = (const float*)d_in[3];
    const int*   gtl    = (const int*)d_in[4];
    float* out = (float*)d_out;

    k_reset<<<1, 256>>>();
    {
        dim3 grid((P + 255) / 256, B);
        k_match<<<grid, 256>>>((const float4*)priors, gtb);
    }
    {
        dim3 grid(P / TILE, B);   // 401 x 16
        k_conf<<<grid, CONF_THREADS>>>(conf, loc, priors, gtb, gtl);
    }
    k_selfin<<<B, SEL_THREADS>>>(out);
}